// round 13
// baseline (speedup 1.0000x reference)
#include <cuda_runtime.h>
#include <cuda_bf16.h>

// FEM H8 stiffness matvec (KU = sum_e scatter(K_type(e) @ gather(U,e))).
// FROZEN v10 design — all cost-model terms addressed; awaiting first
// hardware profile before further mutation.
//
// All passes are plain kernel launches (graph-capturable), scratch lives in
// __device__ globals, every pass rebuilds its state each launch.
//
//   1) k_prep    : pad U [N,3] -> g_u4 [N,4] (16B rows), zero g_acc [N,4],
//                  zero the 64-entry type histogram
//   2) k_histo   : per-block smem histogram; reserves a contiguous range per
//                  (block,type) with ONE global atomic per type per block
//   3) k_scan    : parallel exclusive scan of per-type totals -> g_typeBase
//   4) k_scatter : smem-ranked scatter. Reads each element's nodIdx row
//                  COALESCED and writes permuted connectivity + type byte to
//                  the type-grouped slot (scattered access is a
//                  fire-and-forget store here, not a stalling load in k_main)
//   5) k_main    : matvec over type-grouped elements:
//                  - connectivity/type reads fully coalesced
//                  - warps type-uniform -> Ke loads are L1 broadcasts
//                  - per-node gather = ONE LDG.128 from padded g_u4
//                  - per-node scatter = ONE red.global.add.v4.f32 into g_acc
//   6) k_final   : compact g_acc [N,4] -> out [N,3] with streaming stores
//                  (out is write-once; avoid polluting L2's hot working set
//                  across graph replays). Fully overwrites d_out.

#define N_TYPES 64
#define E_MAX   500000
#define N_MAX   1000000
#define THREADS 256
#define BLOCKS_MAX ((E_MAX + THREADS - 1) / THREADS)

__device__ int           g_typeCount[N_TYPES];               // per-type totals
__device__ int           g_typeBase[N_TYPES];                // exclusive scan
__device__ int           g_blockBase[BLOCKS_MAX * N_TYPES];  // per-(block,type) base
__device__ int4          g_nodIdxPerm[2 * E_MAX];            // permuted connectivity
__device__ unsigned char g_permType[E_MAX];                  // type of permuted element
__device__ float4        g_u4[N_MAX];                        // padded input  [N,4]
__device__ float4        g_acc[N_MAX];                       // padded output accumulator

// vectorized no-return reduction (PTX ISA 8.1+, sm_90+); 16B-aligned target
__device__ __forceinline__ void red_add_v4(float4* addr, float a, float b, float c)
{
    asm volatile("red.global.add.v4.f32 [%0], {%1, %2, %3, %4};"
                 :: "l"(addr), "f"(a), "f"(b), "f"(c), "f"(0.0f)
                 : "memory");
}

// ---- pass 1: pad U, zero accumulator, zero histogram ----
__global__ __launch_bounds__(THREADS) void k_prep(const float* __restrict__ U, int N)
{
    int i = blockIdx.x * THREADS + threadIdx.x;
    if (i < N) {
        g_u4[i]  = make_float4(U[3 * i + 0], U[3 * i + 1], U[3 * i + 2], 0.f);
        g_acc[i] = make_float4(0.f, 0.f, 0.f, 0.f);
    }
    if (blockIdx.x == 0 && threadIdx.x < N_TYPES) g_typeCount[threadIdx.x] = 0;
}

// ---- pass 2: per-block histogram + range reservation ----
__global__ __launch_bounds__(THREADS) void k_histo(const int* __restrict__ types, int E)
{
    __shared__ int h[N_TYPES];
    const int tid = threadIdx.x;
    if (tid < N_TYPES) h[tid] = 0;
    __syncthreads();
    const int e = blockIdx.x * THREADS + tid;
    if (e < E) {
        const int t = types[e] & (N_TYPES - 1);
        atomicAdd(&h[t], 1);
    }
    __syncthreads();
    if (tid < N_TYPES)
        g_blockBase[blockIdx.x * N_TYPES + tid] = atomicAdd(&g_typeCount[tid], h[tid]);
}

// ---- pass 3: parallel exclusive scan over 64 per-type totals ----
__global__ void k_scan()
{
    __shared__ int s[N_TYPES];
    const int tid = threadIdx.x;   // launched with 64 threads
    s[tid] = g_typeCount[tid];
    __syncthreads();
    // Hillis-Steele inclusive scan on 64 entries, then shift to exclusive
#pragma unroll
    for (int d = 1; d < N_TYPES; d <<= 1) {
        int v = (tid >= d) ? s[tid - d] : 0;
        __syncthreads();
        s[tid] += v;
        __syncthreads();
    }
    g_typeBase[tid] = s[tid] - g_typeCount[tid];   // exclusive
}

// ---- pass 4: smem-ranked scatter of permuted connectivity ----
__global__ __launch_bounds__(THREADS) void k_scatter(const int* __restrict__ types,
                                                     const int* __restrict__ nodIdx,
                                                     int E)
{
    __shared__ int h[N_TYPES];
    const int tid = threadIdx.x;
    if (tid < N_TYPES) h[tid] = 0;
    __syncthreads();
    const int e = blockIdx.x * THREADS + tid;
    if (e >= E) return;
    const int t = types[e] & (N_TYPES - 1);
    const int rank = atomicAdd(&h[t], 1);          // cheap smem atomic
    const int pos = g_typeBase[t] + g_blockBase[blockIdx.x * N_TYPES + t] + rank;

    // coalesced read of this element's connectivity, scattered write to the
    // type-grouped slot (runs of ~4 consecutive source elements share lines)
    const int4 na = __ldg(((const int4*)nodIdx) + 2 * e);
    const int4 nb = __ldg(((const int4*)nodIdx) + 2 * e + 1);
    g_nodIdxPerm[2 * pos + 0] = na;
    g_nodIdxPerm[2 * pos + 1] = nb;
    g_permType[pos] = (unsigned char)t;
}

// ---- pass 5: main matvec over permuted (type-grouped) elements ----
__global__ __launch_bounds__(THREADS) void k_main(
    const float* __restrict__ filters,  // [T, 24, 24]
    int E)
{
    const int i = blockIdx.x * THREADS + threadIdx.x;
    if (i >= E) return;

    // fully coalesced: type byte + 32B connectivity
    const int t  = g_permType[i];
    const int4 na = g_nodIdxPerm[2 * i + 0];
    const int4 nb = g_nodIdxPerm[2 * i + 1];
    const int ni[8] = {na.x, na.y, na.z, na.w, nb.x, nb.y, nb.z, nb.w};

    // gather: ONE LDG.128 per node from padded U (L2-resident; 8-deep MLP)
    float ue[24];
#pragma unroll
    for (int k = 0; k < 8; k++) {
        const float4 u = __ldg(&g_u4[ni[k]]);
        ue[3 * k + 0] = u.x;
        ue[3 * k + 1] = u.y;
        ue[3 * k + 2] = u.z;
    }

    // warp-uniform type -> every Ke load is an L1 broadcast (1 wavefront)
    const float* Ke = filters + (size_t)t * 576;

    // fused matvec + scatter: per node, its 3 row-dots, then ONE red.v4
#pragma unroll
    for (int k = 0; k < 8; k++) {
        float f0 = 0.f, f1 = 0.f, f2 = 0.f;
        const float4* r0 = (const float4*)(Ke + (3 * k + 0) * 24);
        const float4* r1 = (const float4*)(Ke + (3 * k + 1) * 24);
        const float4* r2 = (const float4*)(Ke + (3 * k + 2) * 24);
#pragma unroll
        for (int j4 = 0; j4 < 6; j4++) {
            const float u0 = ue[4 * j4 + 0], u1 = ue[4 * j4 + 1];
            const float u2 = ue[4 * j4 + 2], u3 = ue[4 * j4 + 3];
            const float4 a = __ldg(r0 + j4);
            f0 += a.x * u0 + a.y * u1 + a.z * u2 + a.w * u3;
            const float4 b = __ldg(r1 + j4);
            f1 += b.x * u0 + b.y * u1 + b.z * u2 + b.w * u3;
            const float4 c = __ldg(r2 + j4);
            f2 += c.x * u0 + c.y * u1 + c.z * u2 + c.w * u3;
        }
        red_add_v4(&g_acc[ni[k]], f0, f1, f2);
    }
}

// ---- pass 6: compact g_acc [N,4] -> out [N,3], streaming stores ----
__global__ __launch_bounds__(THREADS) void k_final(float* __restrict__ out, int N)
{
    const int n = blockIdx.x * THREADS + threadIdx.x;
    if (n >= N) return;
    const float4 s = g_acc[n];
    __stwt(out + 3 * n + 0, s.x);
    __stwt(out + 3 * n + 1, s.y);
    __stwt(out + 3 * n + 2, s.z);
}

extern "C" void kernel_launch(void* const* d_in, const int* in_sizes, int n_in,
                              void* d_out, int out_size)
{
    const float* U       = (const float*)d_in[0];   // N*3 floats
    const float* filters = (const float*)d_in[1];   // T*24*24 floats
    const int*   types   = (const int*)d_in[2];     // E ints
    const int*   nodIdx  = (const int*)d_in[3];     // E*8 ints

    int E = in_sizes[3] / 8;
    if (E > E_MAX) E = E_MAX;
    int N = in_sizes[0] / 3;
    if (N > N_MAX) N = N_MAX;

    float* out = (float*)d_out;

    const int gridE = (E + THREADS - 1) / THREADS;
    const int gridN = (N + THREADS - 1) / THREADS;

    k_prep<<<gridN, THREADS>>>(U, N);
    k_histo<<<gridE, THREADS>>>(types, E);
    k_scan<<<1, N_TYPES>>>();
    k_scatter<<<gridE, THREADS>>>(types, nodIdx, E);
    k_main<<<gridE, THREADS>>>(filters, E);
    k_final<<<gridN, THREADS>>>(out, N);
}